// round 8
// baseline (speedup 1.0000x reference)
#include <cuda_runtime.h>
#include <math.h>

#define XD 16
#define UD 8
#define AD 32
#define TT 256
#define BB 256
#define T0 8           // Riccati steps computed exactly; converged afterwards
#define CH 16          // time-chunk for means role

// Persistent scratch (device globals — no runtime allocation)
__device__ float gA[XD * XD];
__device__ float gD[XD * AD];
__device__ float gCA[AD * XD];
__device__ float gCB[AD * UD];
__device__ float gJ[T0 * XD * XD];         // posterior information matrices
__device__ float gMT[TT * XD * XD];        // M_t^T : gMT[t][j][i] = M_t[i][j]
__device__ float gV[(size_t)TT * BB * XD]; // v layout [t][b][16]
// Flags for intra-grid producer/consumer sync
__device__ int gPrepFlag;
__device__ int gStepFlag[T0];
__device__ int gGainsFlag[TT];

__device__ __forceinline__ float softplusf(float x) {
    if (x > 20.f) return x;
    return log1pf(expf(x));
}

__device__ __forceinline__ float frcp(float x) {
    float r;
    asm("rcp.approx.ftz.f32 %0, %1;" : "=f"(r) : "f"(x));
    return r;
}

__device__ __forceinline__ void wait_flag(int* f) {
    while (atomicAdd(f, 0) == 0) __nanosleep(50);
}

// ---------------------------------------------------------------------------
// In-register Gauss-Jordan inverse of 16x16 SPD, one warp.
// Layout: lane = j + 16*h owns column j, rows h*8 .. h*8+7 (E[m]).
// ---------------------------------------------------------------------------
__device__ __forceinline__ void reg_inv16(float E[8], int j, int h) {
    const unsigned FULL = 0xffffffffu;
#pragma unroll
    for (int k = 0; k < 16; k++) {
        const int hk = k >> 3;
        const int rk = k & 7;
        float piv = __shfl_sync(FULL, E[rk], k + (hk << 4));
        float p = frcp(piv);
        float rowk = __shfl_sync(FULL, E[rk], j + (hk << 4));
        float colk[8];
#pragma unroll
        for (int m = 0; m < 8; m++) colk[m] = __shfl_sync(FULL, E[m], k + (h << 4));
        float pr = p * rowk;
#pragma unroll
        for (int m = 0; m < 8; m++) {
            int i = (h << 3) + m;
            float En = E[m] - colk[m] * pr;
            if (i == k) En = (j == k) ? p : pr;
            else if (j == k) En = -colk[m] * p;
            E[m] = En;
        }
    }
}

// ---------------------------------------------------------------------------
// Shared-memory Gauss-Jordan inverse of 16x16 SPD (one warp).
// ---------------------------------------------------------------------------
__device__ __forceinline__ void warp_inv16(float (*E)[17], int lane) {
    const int j = lane & 15, h = lane >> 4;
    for (int k = 0; k < 16; k++) {
        float p = 1.0f / E[k][k];
        float rowk = E[k][j];
        float colk[8];
#pragma unroll
        for (int m = 0; m < 8; m++) colk[m] = E[2 * m + h][k];
        __syncwarp();
#pragma unroll
        for (int m = 0; m < 8; m++) {
            int i = 2 * m + h;
            float val;
            if (i == k) {
                val = (j == k) ? p : rowk * p;
            } else if (j == k) {
                val = -colk[m] * p;
            } else {
                val = E[i][j] - colk[m] * (p * rowk);
            }
            E[i][j] = val;
        }
        __syncwarp();
    }
}

// ---------------------------------------------------------------------------
// Register-column MGS QR (positive-diagonal R, matching reference sign fix).
// ---------------------------------------------------------------------------
__device__ __forceinline__ void warp_qr_reg(float x[16], float (*Qs)[17], int lane) {
    const unsigned FULL = 0xffffffffu;
    const int j = lane & 15;
#pragma unroll
    for (int k = 0; k < 16; k++) {
        float qk[16];
#pragma unroll
        for (int i = 0; i < 16; i++) qk[i] = __shfl_sync(FULL, x[i], k);
        float nrm = 0.f;
#pragma unroll
        for (int i = 0; i < 16; i++) nrm += qk[i] * qk[i];
        float inv = rsqrtf(nrm);
#pragma unroll
        for (int i = 0; i < 16; i++) qk[i] *= inv;
        if (lane == k) {
#pragma unroll
            for (int i = 0; i < 16; i++) Qs[i][k] = qk[i];
        }
        float dot = 0.f;
#pragma unroll
        for (int i = 0; i < 16; i++) dot += qk[i] * x[i];
        if (j > k) {
#pragma unroll
            for (int i = 0; i < 16; i++) x[i] -= dot * qk[i];
        }
    }
}

// ---------------------------------------------------------------------------
// Shared-memory role overlays
// ---------------------------------------------------------------------------
struct PrepSmem {
    float sQ[16][17], sU[16][17], sA[16][17], sW[16][17], sZ[16][17], sT[16][17];
    float s1[16], s2[16], nxis[16], nais[32];
};
struct GainsSmem {
    float sE[16][17], sD[16][33], sK[16][33], sA[16][17];
    float sCA[32][17], sCB[32][9], sW[16][9];
    float sa[256 * 33];
};
struct MeansSmem {
    float sMT[CH * 256];
    float sV[8 * CH * 16];
};
#define SMEM_BYTES (sizeof(GainsSmem) > sizeof(MeansSmem) ? \
    (sizeof(GainsSmem) > sizeof(PrepSmem) ? sizeof(GainsSmem) : sizeof(PrepSmem)) : \
    (sizeof(MeansSmem) > sizeof(PrepSmem) ? sizeof(MeansSmem) : sizeof(PrepSmem)))

// ---------------------------------------------------------------------------
// Role 0 (block 0, warp 0): prep + sequential Riccati, publishing flags.
// ---------------------------------------------------------------------------
__device__ void prep_riccati_body(
    char* raw,
    const float* __restrict__ Mmat, const float* __restrict__ Nmat,
    const float* __restrict__ dvec, const float* __restrict__ Bmat,
    const float* __restrict__ Cmat,
    const float* __restrict__ nx, const float* __restrict__ na,
    const float* __restrict__ cov0) {
    PrepSmem* S = reinterpret_cast<PrepSmem*>(raw);
    const unsigned FULL = 0xffffffffu;
    const int lane = threadIdx.x;
    const int j = lane & 15, h = lane >> 4;

    // ---------- QR factors ----------
    {
        float x[16];
#pragma unroll
        for (int i = 0; i < 16; i++) x[i] = Mmat[i * 16 + j];
        warp_qr_reg(x, S->sQ, lane);
#pragma unroll
        for (int i = 0; i < 16; i++) x[i] = Nmat[i * 16 + j];
        warp_qr_reg(x, S->sU, lane);
    }

    if (lane < 16) {
        float dsp = softplusf(dvec[lane]);
        S->s1[lane] = sqrtf(dsp);
        S->s2[lane] = 1.0f / sqrtf(1.0f + dsp);
        S->nxis[lane] = 1.0f / (softplusf(nx[lane]) + 1e-4f);
    }
    S->nais[lane] = 1.0f / (softplusf(na[lane]) + 1e-4f);
    __syncwarp();

    // ---------- A = Uq diag(s1) Q diag(s2) Uq^T ----------
#pragma unroll
    for (int m = 0; m < 8; m++) {
        int i = 2 * m + h;
        float s = 0.f;
#pragma unroll
        for (int k = 0; k < 16; k++) s += S->sU[i][k] * S->s1[k] * S->sQ[k][j];
        S->sW[i][j] = s;
    }
    __syncwarp();
    {
        float Ur[16];
#pragma unroll
        for (int k = 0; k < 16; k++) Ur[k] = S->sU[j][k] * S->s2[k];
#pragma unroll
        for (int m = 0; m < 8; m++) {
            int i = 2 * m + h;
            float s = 0.f;
#pragma unroll
            for (int k = 0; k < 16; k++) s += S->sW[i][k] * Ur[k];
            S->sA[i][j] = s;
            gA[i * 16 + j] = s;
        }
    }
    __syncwarp();

    // ---------- Z, Rc, Gc, D, CA, CB ----------
    float Rc[8], Gc[8], Jr[8], Zr[16];
#pragma unroll
    for (int m = 0; m < 8; m++) {
        int i = 2 * m + h;
        S->sZ[i][j] = S->nxis[i] * S->sA[i][j];
    }
    __syncwarp();
#pragma unroll
    for (int m = 0; m < 8; m++) {
        int i = (h << 3) + m;
        float s = 0.f;
#pragma unroll
        for (int k = 0; k < 16; k++) s += S->sA[k][i] * S->nxis[k] * S->sA[k][j];
        Rc[m] = s;
    }
#pragma unroll
    for (int m = 0; m < 8; m++) {
        int i = (h << 3) + m;
        float s = 0.f;
#pragma unroll
        for (int k = 0; k < 32; k++) s += Cmat[k * 16 + i] * S->nais[k] * Cmat[k * 16 + j];
        Gc[m] = s;
    }
    for (int e = lane; e < 512; e += 32) {
        int i = e >> 5, c = e & 31;
        gD[i * 32 + c] = Cmat[c * 16 + i] * S->nais[c];
    }
    {
        float Crow[16];
#pragma unroll
        for (int k = 0; k < 16; k++) Crow[k] = Cmat[lane * 16 + k];
#pragma unroll
        for (int jj = 0; jj < 16; jj++) {
            float s = 0.f;
#pragma unroll
            for (int k = 0; k < 16; k++) s += Crow[k] * S->sA[k][jj];
            gCA[lane * 16 + jj] = s;
        }
#pragma unroll
        for (int jj = 0; jj < 8; jj++) {
            float s = 0.f;
#pragma unroll
            for (int k = 0; k < 16; k++) s += Crow[k] * Bmat[k * 8 + jj];
            gCB[lane * 8 + jj] = s;
        }
    }

    // Publish constants (gA, gD, gCA, gCB all stored above)
    __threadfence();
    __syncwarp();
    if (lane == 0) atomicExch(&gPrepFlag, 1);

#pragma unroll
    for (int k = 0; k < 16; k++) Zr[k] = S->sZ[j][k];
    float nxij = S->nxis[j];

    // J0 = inv(cov0[0]) — register GJ (riccati layout)
#pragma unroll
    for (int m = 0; m < 8; m++) Jr[m] = cov0[((h << 3) + m) * 16 + j];
    reg_inv16(Jr, j, h);
    __syncwarp();

    // ---------- Riccati: E=J+R0 ; F=E^-1 ; Jm=diag(nxi)-Z F Z^T ; J=Jm+G ----------
    for (int t = 0; t < T0; t++) {
        float E[8];
#pragma unroll
        for (int m = 0; m < 8; m++) E[m] = Jr[m] + Rc[m];
        reg_inv16(E, j, h);

        float Fc[16];
#pragma unroll
        for (int m = 0; m < 8; m++) {
            Fc[(h << 3) + m] = E[m];
            Fc[((1 - h) << 3) + m] = __shfl_xor_sync(FULL, E[m], 16);
        }

#pragma unroll
        for (int m = 0; m < 8; m++) {
            int i = (h << 3) + m;
            float s0 = 0.f, s1a = 0.f;
#pragma unroll
            for (int k = 0; k < 8; k++) {
                s0 += S->sZ[i][2 * k] * Fc[2 * k];
                s1a += S->sZ[i][2 * k + 1] * Fc[2 * k + 1];
            }
            S->sT[i][j] = s0 + s1a;
        }
        __syncwarp();

        float* gj = gJ + t * 256;
#pragma unroll
        for (int m = 0; m < 8; m++) {
            int i = (h << 3) + m;
            float s0 = (i == j) ? nxij : 0.f, s1a = 0.f;
#pragma unroll
            for (int k = 0; k < 8; k++) {
                s0 -= S->sT[i][2 * k] * Zr[2 * k];
                s1a -= S->sT[i][2 * k + 1] * Zr[2 * k + 1];
            }
            float jn = s0 + s1a + Gc[m];
            gj[i * 16 + j] = jn;
            Jr[m] = jn;
        }
        // publish step t
        __threadfence();
        __syncwarp();
        if (lane == 0) atomicExch(&gStepFlag[t], 1);
    }
}

// ---------------------------------------------------------------------------
// Role 1 (blocks 1..TT): per-t gains + v.
// ---------------------------------------------------------------------------
__device__ void gainsv_body(char* raw, int t,
                            const float* __restrict__ Bmat,
                            const float* __restrict__ u,
                            const float* __restrict__ a) {
    GainsSmem* S = reinterpret_cast<GainsSmem*>(raw);
    const int ts = (t < T0) ? t : (T0 - 1);
    const int tid = threadIdx.x;
    const int lane = tid & 31;

    if (tid < 32) {
        // wait for constants, then stage them
        if (lane == 0) wait_flag(&gPrepFlag);
        __syncwarp();
        __threadfence();
        for (int e = lane; e < 512; e += 32) S->sD[e >> 5][e & 31] = gD[e];
        for (int e = lane; e < 256; e += 32) S->sA[e >> 4][e & 15] = gA[e];
        for (int e = lane; e < 512; e += 32) S->sCA[e >> 4][e & 15] = gCA[e];
        for (int e = lane; e < 256; e += 32) S->sCB[e >> 3][e & 7] = gCB[e];
        // wait for J_ts
        if (lane == 0) wait_flag(&gStepFlag[ts]);
        __syncwarp();
        __threadfence();
        for (int e = lane; e < 256; e += 32) S->sE[e >> 4][e & 15] = gJ[ts * 256 + e];
        __syncwarp();
        warp_inv16(S->sE, lane);
#pragma unroll
        for (int r = 0; r < 16; r++) {
            float s = 0.f;
#pragma unroll
            for (int m = 0; m < 16; m++) s += S->sE[r][m] * S->sD[m][lane];
            S->sK[r][lane] = s;
        }
    } else {
        // stage a[:, t, :] tile (no dependencies — overlaps the riccati chain)
        for (int e = tid - 32; e < 256 * 32; e += 224) {
            int b = e >> 5, c = e & 31;
            S->sa[b * 33 + c] = a[((size_t)b * TT + t) * 32 + c];
        }
    }
    __syncthreads();

    // M (256 elems) and W (128 elems)
    {
        int i = tid & 15, jj = tid >> 4;
        float s = S->sA[i][jj];
#pragma unroll
        for (int l = 0; l < 32; l++) s -= S->sK[i][l] * S->sCA[l][jj];
        gMT[t * 256 + tid] = s;
    }
    if (tid < 128) {
        int i = tid >> 3, jw = tid & 7;
        float s = Bmat[i * 8 + jw];
#pragma unroll
        for (int l = 0; l < 32; l++) s -= S->sK[i][l] * S->sCB[l][jw];
        S->sW[i][jw] = s;
    }
    __syncthreads();

    // v_{b,t}: thread = b
    {
        const int b = tid;
        const float4* up = reinterpret_cast<const float4*>(u + ((size_t)b * TT + t) * 8);
        float4 u0 = up[0], u1 = up[1];
        float uu[8] = {u0.x, u0.y, u0.z, u0.w, u1.x, u1.y, u1.z, u1.w};
        float aa[32];
#pragma unroll
        for (int c = 0; c < 32; c++) aa[c] = S->sa[b * 33 + c];
        float v[16];
#pragma unroll
        for (int i = 0; i < 16; i++) {
            float s = 0.f;
#pragma unroll
            for (int k = 0; k < 8; k++) s += S->sW[i][k] * uu[k];
#pragma unroll
            for (int l = 0; l < 32; l++) s += S->sK[i][l] * aa[l];
            v[i] = s;
        }
        float4* vp = reinterpret_cast<float4*>(gV + ((size_t)t * BB + b) * 16);
#pragma unroll
        for (int q = 0; q < 4; q++)
            vp[q] = make_float4(v[4 * q], v[4 * q + 1], v[4 * q + 2], v[4 * q + 3]);
    }

    // publish completion of this t
    __threadfence();
    __syncthreads();
    if (tid == 0) atomicExch(&gGainsFlag[t], 1);
}

// ---------------------------------------------------------------------------
// Role 2 (blocks TT+1 .. TT+32): mean recurrence, 8 batches per block.
// ---------------------------------------------------------------------------
__device__ void means_body(char* raw, int mb,
                           const float* __restrict__ mean0,
                           float* __restrict__ out) {
    MeansSmem* S = reinterpret_cast<MeansSmem*>(raw);
    const unsigned FULL = 0xffffffffu;
    const int w = threadIdx.x >> 5;
    const int lane = threadIdx.x & 31;
    const int i = lane & 15;
    const int b = mb * 8 + w;

    float mean = mean0[b * 16 + i];
    float* ob = out + (size_t)b * TT * 16;

    for (int c = 0; c < TT / CH; c++) {
        // wait until all t in this chunk are produced
        if (threadIdx.x < CH) wait_flag(&gGainsFlag[c * CH + threadIdx.x]);
        __syncthreads();
        __threadfence();
        for (int e = threadIdx.x; e < CH * 256; e += 256)
            S->sMT[e] = gMT[c * (CH * 256) + e];
        for (int e = threadIdx.x; e < 8 * CH * 16; e += 256) {
            int wb = e >> 8;           // CH*16 == 256
            int rem = e & 255;
            int tt = rem >> 4, ii = rem & 15;
            S->sV[e] = gV[((size_t)(c * CH + tt) * BB + (mb * 8 + wb)) * 16 + ii];
        }
        __syncthreads();

#pragma unroll 4
        for (int tt = 0; tt < CH; tt++) {
            const float* Mp = &S->sMT[tt * 256];
            float a0 = S->sV[(w * CH + tt) * 16 + i], a1 = 0.f, a2 = 0.f, a3 = 0.f;
#pragma unroll
            for (int k = 0; k < 4; k++) {
                a0 += Mp[(4 * k + 0) * 16 + i] * __shfl_sync(FULL, mean, 4 * k + 0, 16);
                a1 += Mp[(4 * k + 1) * 16 + i] * __shfl_sync(FULL, mean, 4 * k + 1, 16);
                a2 += Mp[(4 * k + 2) * 16 + i] * __shfl_sync(FULL, mean, 4 * k + 2, 16);
                a3 += Mp[(4 * k + 3) * 16 + i] * __shfl_sync(FULL, mean, 4 * k + 3, 16);
            }
            mean = (a0 + a1) + (a2 + a3);
            if (lane < 16) ob[(c * CH + tt) * 16 + i] = mean;
        }
        __syncthreads();
    }
}

// ---------------------------------------------------------------------------
// Flag-clear kernel (runs before the fused kernel each launch)
// ---------------------------------------------------------------------------
__global__ void clear_kernel() {
    int i = threadIdx.x;
    if (i < TT) gGainsFlag[i] = 0;
    if (i < T0) gStepFlag[i] = 0;
    if (i == 0) gPrepFlag = 0;
}

// ---------------------------------------------------------------------------
// Fused mega-kernel: 1 + TT + 32 blocks. launch_bounds(256,2) guarantees all
// 289 blocks are co-resident (2 blocks/SM x 148 SMs), making spins safe.
// ---------------------------------------------------------------------------
__global__ void __launch_bounds__(256, 2) fused_kernel(
    const float* __restrict__ mean0, const float* __restrict__ cov0,
    const float* __restrict__ u, const float* __restrict__ a,
    const float* __restrict__ Mmat, const float* __restrict__ Nmat,
    const float* __restrict__ dvec, const float* __restrict__ Bmat,
    const float* __restrict__ Cmat,
    const float* __restrict__ nx, const float* __restrict__ na,
    float* __restrict__ out) {
    __shared__ __align__(16) char raw[SMEM_BYTES];
    const int bid = blockIdx.x;
    if (bid == 0) {
        if (threadIdx.x < 32)
            prep_riccati_body(raw, Mmat, Nmat, dvec, Bmat, Cmat, nx, na, cov0);
    } else if (bid <= TT) {
        gainsv_body(raw, bid - 1, Bmat, u, a);
    } else {
        means_body(raw, bid - 1 - TT, mean0, out);
    }
}

// ---------------------------------------------------------------------------
extern "C" void kernel_launch(void* const* d_in, const int* in_sizes, int n_in,
                              void* d_out, int out_size) {
    const float* mean0 = (const float*)d_in[0];
    const float* cov0  = (const float*)d_in[1];
    const float* u     = (const float*)d_in[2];
    const float* a     = (const float*)d_in[3];
    const float* Mmat  = (const float*)d_in[4];
    const float* Nmat  = (const float*)d_in[5];
    const float* dvec  = (const float*)d_in[6];
    const float* Bmat  = (const float*)d_in[7];
    const float* Cmat  = (const float*)d_in[8];
    const float* nx    = (const float*)d_in[9];
    const float* na    = (const float*)d_in[10];
    float* out = (float*)d_out;

    clear_kernel<<<1, 256>>>();
    fused_kernel<<<1 + TT + 32, 256>>>(mean0, cov0, u, a, Mmat, Nmat, dvec,
                                       Bmat, Cmat, nx, na, out);
}

// round 9
// speedup vs baseline: 1.0421x; 1.0421x over previous
#include <cuda_runtime.h>
#include <math.h>

#define XD 16
#define UD 8
#define AD 32
#define TT 256
#define BB 256
#define T0 8           // Riccati steps computed exactly; converged afterwards
#define CH 16          // time-chunk for means role

// Persistent scratch (device globals — no runtime allocation)
__device__ float gA[XD * XD];
__device__ float gD[XD * AD];
__device__ float gCA[AD * XD];
__device__ float gCB[AD * UD];
__device__ float gJ[T0 * XD * XD];         // posterior information matrices
__device__ float gMT[TT * XD * XD];        // M_t^T : gMT[t][j][i] = M_t[i][j]
__device__ float gV[(size_t)TT * BB * XD]; // v layout [t][b][16]
// Flags for intra-grid producer/consumer sync
__device__ int gPrepFlag;
__device__ int gStepFlag[T0];
__device__ int gGainsFlag[TT];

__device__ __forceinline__ float softplusf(float x) {
    if (x > 20.f) return x;
    return log1pf(expf(x));
}

__device__ __forceinline__ float frcp(float x) {
    float r;
    asm("rcp.approx.ftz.f32 %0, %1;" : "=f"(r) : "f"(x));
    return r;
}

// Plain-load polling (no RMW serialization at the LTS under 250 spinners)
__device__ __forceinline__ void wait_flag(int* f) {
    while (*((volatile int*)f) == 0) __nanosleep(100);
}

// ---------------------------------------------------------------------------
// In-register Gauss-Jordan inverse of 16x16 SPD, one warp.
// Layout: lane = j + 16*h owns column j, rows h*8 .. h*8+7 (E[m]).
// ---------------------------------------------------------------------------
__device__ __forceinline__ void reg_inv16(float E[8], int j, int h) {
    const unsigned FULL = 0xffffffffu;
#pragma unroll
    for (int k = 0; k < 16; k++) {
        const int hk = k >> 3;
        const int rk = k & 7;
        float piv = __shfl_sync(FULL, E[rk], k + (hk << 4));
        float p = frcp(piv);
        float rowk = __shfl_sync(FULL, E[rk], j + (hk << 4));
        float colk[8];
#pragma unroll
        for (int m = 0; m < 8; m++) colk[m] = __shfl_sync(FULL, E[m], k + (h << 4));
        float pr = p * rowk;
#pragma unroll
        for (int m = 0; m < 8; m++) {
            int i = (h << 3) + m;
            float En = E[m] - colk[m] * pr;
            if (i == k) En = (j == k) ? p : pr;
            else if (j == k) En = -colk[m] * p;
            E[m] = En;
        }
    }
}

// ---------------------------------------------------------------------------
// Shared-memory Gauss-Jordan inverse of 16x16 SPD (one warp).
// ---------------------------------------------------------------------------
__device__ __forceinline__ void warp_inv16(float (*E)[17], int lane) {
    const int j = lane & 15, h = lane >> 4;
    for (int k = 0; k < 16; k++) {
        float p = 1.0f / E[k][k];
        float rowk = E[k][j];
        float colk[8];
#pragma unroll
        for (int m = 0; m < 8; m++) colk[m] = E[2 * m + h][k];
        __syncwarp();
#pragma unroll
        for (int m = 0; m < 8; m++) {
            int i = 2 * m + h;
            float val;
            if (i == k) {
                val = (j == k) ? p : rowk * p;
            } else if (j == k) {
                val = -colk[m] * p;
            } else {
                val = E[i][j] - colk[m] * (p * rowk);
            }
            E[i][j] = val;
        }
        __syncwarp();
    }
}

// ---------------------------------------------------------------------------
// Register-column MGS QR (positive-diagonal R, matching reference sign fix).
// ---------------------------------------------------------------------------
__device__ __forceinline__ void warp_qr_reg(float x[16], float (*Qs)[17], int lane) {
    const unsigned FULL = 0xffffffffu;
    const int j = lane & 15;
#pragma unroll
    for (int k = 0; k < 16; k++) {
        float qk[16];
#pragma unroll
        for (int i = 0; i < 16; i++) qk[i] = __shfl_sync(FULL, x[i], k);
        float nrm = 0.f;
#pragma unroll
        for (int i = 0; i < 16; i++) nrm += qk[i] * qk[i];
        float inv = rsqrtf(nrm);
#pragma unroll
        for (int i = 0; i < 16; i++) qk[i] *= inv;
        if (lane == k) {
#pragma unroll
            for (int i = 0; i < 16; i++) Qs[i][k] = qk[i];
        }
        float dot = 0.f;
#pragma unroll
        for (int i = 0; i < 16; i++) dot += qk[i] * x[i];
        if (j > k) {
#pragma unroll
            for (int i = 0; i < 16; i++) x[i] -= dot * qk[i];
        }
    }
}

// ---------------------------------------------------------------------------
// Shared-memory role overlays
// ---------------------------------------------------------------------------
struct PrepSmem {
    float sQ[16][17], sU[16][17], sW[16][17], sA[16][17];
    float sZ[16][17], sT[16][17], sRc[16][17], sGc[16][17], sJ0[16][17];
    float s1[16], s2[16], nxis[16], nais[32];
};
struct GainsSmem {
    float sE[16][17], sD[16][33], sK[16][33], sA[16][17];
    float sCA[32][17], sCB[32][9], sW[16][9];
    float sa[256 * 33];
};
struct MeansSmem {
    float sMT[CH * 256];
    float sV[8 * CH * 16];
};
#define SMEM_BYTES (sizeof(GainsSmem) > sizeof(MeansSmem) ? \
    (sizeof(GainsSmem) > sizeof(PrepSmem) ? sizeof(GainsSmem) : sizeof(PrepSmem)) : \
    (sizeof(MeansSmem) > sizeof(PrepSmem) ? sizeof(MeansSmem) : sizeof(PrepSmem)))

// ---------------------------------------------------------------------------
// Role 0 (block 0, all 256 threads for prep; warp 0 for riccati).
// ---------------------------------------------------------------------------
__device__ void prep_riccati_body(
    char* raw,
    const float* __restrict__ Mmat, const float* __restrict__ Nmat,
    const float* __restrict__ dvec, const float* __restrict__ Bmat,
    const float* __restrict__ Cmat,
    const float* __restrict__ nx, const float* __restrict__ na,
    const float* __restrict__ cov0) {
    PrepSmem* S = reinterpret_cast<PrepSmem*>(raw);
    const unsigned FULL = 0xffffffffu;
    const int tid = threadIdx.x;
    const int wid = tid >> 5;
    const int lane = tid & 31;
    const int i16 = tid >> 4;   // 0..15 row index for element-per-thread phases
    const int j16 = tid & 15;   // 0..15 col index

    // ======== Phase 1: independent pieces, one warp each ========
    if (wid == 0) {
        float x[16];
#pragma unroll
        for (int i = 0; i < 16; i++) x[i] = Mmat[i * 16 + (lane & 15)];
        warp_qr_reg(x, S->sQ, lane);
    } else if (wid == 1) {
        float x[16];
#pragma unroll
        for (int i = 0; i < 16; i++) x[i] = Nmat[i * 16 + (lane & 15)];
        warp_qr_reg(x, S->sU, lane);
    } else if (wid == 2) {
        if (lane < 16) {
            float dsp = softplusf(dvec[lane]);
            S->s1[lane] = sqrtf(dsp);
            S->s2[lane] = 1.0f / sqrtf(1.0f + dsp);
            S->nxis[lane] = 1.0f / (softplusf(nx[lane]) + 1e-4f);
        }
        S->nais[lane] = 1.0f / (softplusf(na[lane]) + 1e-4f);
    } else if (wid == 3) {
        // J0 = inv(cov0[0])
        for (int e = lane; e < 256; e += 32) S->sJ0[e >> 4][e & 15] = cov0[e];
        __syncwarp();
        warp_inv16(S->sJ0, lane);
    } else if (wid == 4) {
        // CB = C*B (32x8): lane = C row
        float Crow[16];
#pragma unroll
        for (int k = 0; k < 16; k++) Crow[k] = Cmat[lane * 16 + k];
#pragma unroll
        for (int jj = 0; jj < 8; jj++) {
            float s = 0.f;
#pragma unroll
            for (int k = 0; k < 16; k++) s += Crow[k] * Bmat[k * 8 + jj];
            gCB[lane * 8 + jj] = s;
        }
    }
    __syncthreads();

    // ======== Phase 2: W = Uq diag(s1) Q ; Gc = C^T diag(nai) C ; gD ========
    {
        float s = 0.f;
#pragma unroll
        for (int k = 0; k < 16; k++) s += S->sU[i16][k] * S->s1[k] * S->sQ[k][j16];
        S->sW[i16][j16] = s;
        float g = 0.f;
#pragma unroll
        for (int c = 0; c < 32; c++)
            g += Cmat[c * 16 + i16] * S->nais[c] * Cmat[c * 16 + j16];
        S->sGc[i16][j16] = g;
        // gD: 512 elems, 2 per thread. gD[i][c] = C[c][i]*nai[c]
#pragma unroll
        for (int r = 0; r < 2; r++) {
            int e = tid + r * 256;
            int di = e >> 5, dc = e & 31;
            gD[di * 32 + dc] = Cmat[dc * 16 + di] * S->nais[dc];
        }
    }
    __syncthreads();

    // ======== Phase 3: A = W diag(s2) Uq^T ========
    {
        float s = 0.f;
#pragma unroll
        for (int k = 0; k < 16; k++) s += S->sW[i16][k] * S->s2[k] * S->sU[j16][k];
        S->sA[i16][j16] = s;
        gA[i16 * 16 + j16] = s;
    }
    __syncthreads();

    // ======== Phase 4: Z, R0, CA ========
    {
        S->sZ[i16][j16] = S->nxis[i16] * S->sA[i16][j16];
        float s = 0.f;
#pragma unroll
        for (int k = 0; k < 16; k++)
            s += S->sA[k][i16] * S->nxis[k] * S->sA[k][j16];
        S->sRc[i16][j16] = s;
        // CA = C*A (32x16): 512 elems, 2 per thread
#pragma unroll
        for (int r = 0; r < 2; r++) {
            int e = tid + r * 256;
            int c = e >> 4, jj = e & 15;
            float sca = 0.f;
#pragma unroll
            for (int k = 0; k < 16; k++) sca += Cmat[c * 16 + k] * S->sA[k][jj];
            gCA[c * 16 + jj] = sca;
        }
    }
    // Publish constants (gA, gD, gCA, gCB)
    __threadfence();
    __syncthreads();
    if (tid == 0) atomicExch(&gPrepFlag, 1);

    // ======== Phase 5: Riccati, warp 0 only ========
    if (wid != 0) return;
    const int j = lane & 15, h = lane >> 4;
    float Rc[8], Gc[8], Jr[8], Zr[16];
#pragma unroll
    for (int m = 0; m < 8; m++) {
        int i = (h << 3) + m;
        Rc[m] = S->sRc[i][j];
        Gc[m] = S->sGc[i][j];
        Jr[m] = S->sJ0[i][j];
    }
#pragma unroll
    for (int k = 0; k < 16; k++) Zr[k] = S->sZ[j][k];
    float nxij = S->nxis[j];
    __syncwarp();

    for (int t = 0; t < T0; t++) {
        float E[8];
#pragma unroll
        for (int m = 0; m < 8; m++) E[m] = Jr[m] + Rc[m];
        reg_inv16(E, j, h);

        float Fc[16];
#pragma unroll
        for (int m = 0; m < 8; m++) {
            Fc[(h << 3) + m] = E[m];
            Fc[((1 - h) << 3) + m] = __shfl_xor_sync(FULL, E[m], 16);
        }

#pragma unroll
        for (int m = 0; m < 8; m++) {
            int i = (h << 3) + m;
            float s0 = 0.f, s1a = 0.f;
#pragma unroll
            for (int k = 0; k < 8; k++) {
                s0 += S->sZ[i][2 * k] * Fc[2 * k];
                s1a += S->sZ[i][2 * k + 1] * Fc[2 * k + 1];
            }
            S->sT[i][j] = s0 + s1a;
        }
        __syncwarp();

        float* gj = gJ + t * 256;
#pragma unroll
        for (int m = 0; m < 8; m++) {
            int i = (h << 3) + m;
            float s0 = (i == j) ? nxij : 0.f, s1a = 0.f;
#pragma unroll
            for (int k = 0; k < 8; k++) {
                s0 -= S->sT[i][2 * k] * Zr[2 * k];
                s1a -= S->sT[i][2 * k + 1] * Zr[2 * k + 1];
            }
            float jn = s0 + s1a + Gc[m];
            gj[i * 16 + j] = jn;
            Jr[m] = jn;
        }
        __threadfence();
        __syncwarp();
        if (lane == 0) atomicExch(&gStepFlag[t], 1);
    }
}

// ---------------------------------------------------------------------------
// Role 1 (blocks 1..TT): per-t gains + v.
// ---------------------------------------------------------------------------
__device__ void gainsv_body(char* raw, int t,
                            const float* __restrict__ Bmat,
                            const float* __restrict__ u,
                            const float* __restrict__ a) {
    GainsSmem* S = reinterpret_cast<GainsSmem*>(raw);
    const int ts = (t < T0) ? t : (T0 - 1);
    const int tid = threadIdx.x;
    const int lane = tid & 31;

    if (tid < 32) {
        // wait for constants, then stage them
        if (lane == 0) wait_flag(&gPrepFlag);
        __syncwarp();
        __threadfence();
        for (int e = lane; e < 512; e += 32) S->sD[e >> 5][e & 31] = gD[e];
        for (int e = lane; e < 256; e += 32) S->sA[e >> 4][e & 15] = gA[e];
        for (int e = lane; e < 512; e += 32) S->sCA[e >> 4][e & 15] = gCA[e];
        for (int e = lane; e < 256; e += 32) S->sCB[e >> 3][e & 7] = gCB[e];
        // wait for J_ts
        if (lane == 0) wait_flag(&gStepFlag[ts]);
        __syncwarp();
        __threadfence();
        for (int e = lane; e < 256; e += 32) S->sE[e >> 4][e & 15] = gJ[ts * 256 + e];
        __syncwarp();
        warp_inv16(S->sE, lane);
#pragma unroll
        for (int r = 0; r < 16; r++) {
            float s = 0.f;
#pragma unroll
            for (int m = 0; m < 16; m++) s += S->sE[r][m] * S->sD[m][lane];
            S->sK[r][lane] = s;
        }
    } else {
        // stage a[:, t, :] tile (no dependencies — overlaps the riccati chain)
        for (int e = tid - 32; e < 256 * 32; e += 224) {
            int b = e >> 5, c = e & 31;
            S->sa[b * 33 + c] = a[((size_t)b * TT + t) * 32 + c];
        }
    }
    __syncthreads();

    // M (256 elems) and W (128 elems)
    {
        int i = tid & 15, jj = tid >> 4;
        float s = S->sA[i][jj];
#pragma unroll
        for (int l = 0; l < 32; l++) s -= S->sK[i][l] * S->sCA[l][jj];
        gMT[t * 256 + tid] = s;
    }
    if (tid < 128) {
        int i = tid >> 3, jw = tid & 7;
        float s = Bmat[i * 8 + jw];
#pragma unroll
        for (int l = 0; l < 32; l++) s -= S->sK[i][l] * S->sCB[l][jw];
        S->sW[i][jw] = s;
    }
    __syncthreads();

    // v_{b,t}: thread = b
    {
        const int b = tid;
        const float4* up = reinterpret_cast<const float4*>(u + ((size_t)b * TT + t) * 8);
        float4 u0 = up[0], u1 = up[1];
        float uu[8] = {u0.x, u0.y, u0.z, u0.w, u1.x, u1.y, u1.z, u1.w};
        float aa[32];
#pragma unroll
        for (int c = 0; c < 32; c++) aa[c] = S->sa[b * 33 + c];
        float v[16];
#pragma unroll
        for (int i = 0; i < 16; i++) {
            float s = 0.f;
#pragma unroll
            for (int k = 0; k < 8; k++) s += S->sW[i][k] * uu[k];
#pragma unroll
            for (int l = 0; l < 32; l++) s += S->sK[i][l] * aa[l];
            v[i] = s;
        }
        float4* vp = reinterpret_cast<float4*>(gV + ((size_t)t * BB + b) * 16);
#pragma unroll
        for (int q = 0; q < 4; q++)
            vp[q] = make_float4(v[4 * q], v[4 * q + 1], v[4 * q + 2], v[4 * q + 3]);
    }

    __threadfence();
    __syncthreads();
    if (tid == 0) atomicExch(&gGainsFlag[t], 1);
}

// ---------------------------------------------------------------------------
// Role 2 (blocks TT+1 .. TT+32): mean recurrence, 8 batches per block.
// ---------------------------------------------------------------------------
__device__ void means_body(char* raw, int mb,
                           const float* __restrict__ mean0,
                           float* __restrict__ out) {
    MeansSmem* S = reinterpret_cast<MeansSmem*>(raw);
    const unsigned FULL = 0xffffffffu;
    const int w = threadIdx.x >> 5;
    const int lane = threadIdx.x & 31;
    const int i = lane & 15;
    const int b = mb * 8 + w;

    float mean = mean0[b * 16 + i];
    float* ob = out + (size_t)b * TT * 16;

    for (int c = 0; c < TT / CH; c++) {
        if (threadIdx.x < CH) wait_flag(&gGainsFlag[c * CH + threadIdx.x]);
        __syncthreads();
        __threadfence();
        for (int e = threadIdx.x; e < CH * 256; e += 256)
            S->sMT[e] = gMT[c * (CH * 256) + e];
        for (int e = threadIdx.x; e < 8 * CH * 16; e += 256) {
            int wb = e >> 8;           // CH*16 == 256
            int rem = e & 255;
            int tt = rem >> 4, ii = rem & 15;
            S->sV[e] = gV[((size_t)(c * CH + tt) * BB + (mb * 8 + wb)) * 16 + ii];
        }
        __syncthreads();

#pragma unroll 4
        for (int tt = 0; tt < CH; tt++) {
            const float* Mp = &S->sMT[tt * 256];
            float a0 = S->sV[(w * CH + tt) * 16 + i], a1 = 0.f, a2 = 0.f, a3 = 0.f;
#pragma unroll
            for (int k = 0; k < 4; k++) {
                a0 += Mp[(4 * k + 0) * 16 + i] * __shfl_sync(FULL, mean, 4 * k + 0, 16);
                a1 += Mp[(4 * k + 1) * 16 + i] * __shfl_sync(FULL, mean, 4 * k + 1, 16);
                a2 += Mp[(4 * k + 2) * 16 + i] * __shfl_sync(FULL, mean, 4 * k + 2, 16);
                a3 += Mp[(4 * k + 3) * 16 + i] * __shfl_sync(FULL, mean, 4 * k + 3, 16);
            }
            mean = (a0 + a1) + (a2 + a3);
            if (lane < 16) ob[(c * CH + tt) * 16 + i] = mean;
        }
        __syncthreads();
    }
}

// ---------------------------------------------------------------------------
// Flag-clear kernel (runs before the fused kernel each launch)
// ---------------------------------------------------------------------------
__global__ void clear_kernel() {
    int i = threadIdx.x;
    if (i < TT) gGainsFlag[i] = 0;
    if (i < T0) gStepFlag[i] = 0;
    if (i == 0) gPrepFlag = 0;
}

// ---------------------------------------------------------------------------
// Fused mega-kernel: 1 + TT + 32 blocks. No occupancy cap (riccati role needs
// its full register budget). Deadlock-free: dependency graph is a DAG and
// block 0 (the root producer) is scheduled in the first wave.
// ---------------------------------------------------------------------------
__global__ void __launch_bounds__(256) fused_kernel(
    const float* __restrict__ mean0, const float* __restrict__ cov0,
    const float* __restrict__ u, const float* __restrict__ a,
    const float* __restrict__ Mmat, const float* __restrict__ Nmat,
    const float* __restrict__ dvec, const float* __restrict__ Bmat,
    const float* __restrict__ Cmat,
    const float* __restrict__ nx, const float* __restrict__ na,
    float* __restrict__ out) {
    __shared__ __align__(16) char raw[SMEM_BYTES];
    const int bid = blockIdx.x;
    if (bid == 0) {
        prep_riccati_body(raw, Mmat, Nmat, dvec, Bmat, Cmat, nx, na, cov0);
    } else if (bid <= TT) {
        gainsv_body(raw, bid - 1, Bmat, u, a);
    } else {
        means_body(raw, bid - 1 - TT, mean0, out);
    }
}

// ---------------------------------------------------------------------------
extern "C" void kernel_launch(void* const* d_in, const int* in_sizes, int n_in,
                              void* d_out, int out_size) {
    const float* mean0 = (const float*)d_in[0];
    const float* cov0  = (const float*)d_in[1];
    const float* u     = (const float*)d_in[2];
    const float* a     = (const float*)d_in[3];
    const float* Mmat  = (const float*)d_in[4];
    const float* Nmat  = (const float*)d_in[5];
    const float* dvec  = (const float*)d_in[6];
    const float* Bmat  = (const float*)d_in[7];
    const float* Cmat  = (const float*)d_in[8];
    const float* nx    = (const float*)d_in[9];
    const float* na    = (const float*)d_in[10];
    float* out = (float*)d_out;

    clear_kernel<<<1, 256>>>();
    fused_kernel<<<1 + TT + 32, 256>>>(mean0, cov0, u, a, Mmat, Nmat, dvec,
                                       Bmat, Cmat, nx, na, out);
}

// round 14
// speedup vs baseline: 1.0703x; 1.0270x over previous
#include <cuda_runtime.h>
#include <math.h>

#define XD 16
#define UD 8
#define AD 32
#define TT 256
#define BB 256
#define T0 8           // Riccati steps computed exactly; converged afterwards
#define CH 32          // time-chunk for means role (8 chunks total)

// Persistent scratch (device globals — no runtime allocation)
__device__ float gA[XD * XD];
__device__ float gD[XD * AD];
__device__ float gCA[AD * XD];
__device__ float gCB[AD * UD];
__device__ float gJ[T0 * XD * XD];         // posterior information matrices
__device__ float gMT[TT * XD * XD];        // M_t^T : gMT[t][j][i] = M_t[i][j]
__device__ float gV[(size_t)TT * BB * XD]; // v layout [t][b][16]
// Flags for intra-grid producer/consumer sync
__device__ int gPrepFlag;
__device__ int gStepFlag[T0];
__device__ int gGainsFlag[TT];

__device__ __forceinline__ float softplusf(float x) {
    if (x > 20.f) return x;
    return log1pf(expf(x));
}

__device__ __forceinline__ float frcp(float x) {
    float r;
    asm("rcp.approx.ftz.f32 %0, %1;" : "=f"(r) : "f"(x));
    return r;
}

// Plain-load polling (no RMW serialization at the LTS under 250 spinners)
__device__ __forceinline__ void wait_flag(int* f) {
    while (*((volatile int*)f) == 0) __nanosleep(100);
}

// ---------------------------------------------------------------------------
// In-register Gauss-Jordan inverse of 16x16 SPD, one warp.
// Layout: lane = j + 16*h owns column j, rows h*8 .. h*8+7 (E[m]).
// ---------------------------------------------------------------------------
__device__ __forceinline__ void reg_inv16(float E[8], int j, int h) {
    const unsigned FULL = 0xffffffffu;
#pragma unroll
    for (int k = 0; k < 16; k++) {
        const int hk = k >> 3;
        const int rk = k & 7;
        float piv = __shfl_sync(FULL, E[rk], k + (hk << 4));
        float p = frcp(piv);
        float rowk = __shfl_sync(FULL, E[rk], j + (hk << 4));
        float colk[8];
#pragma unroll
        for (int m = 0; m < 8; m++) colk[m] = __shfl_sync(FULL, E[m], k + (h << 4));
        float pr = p * rowk;
#pragma unroll
        for (int m = 0; m < 8; m++) {
            int i = (h << 3) + m;
            float En = E[m] - colk[m] * pr;
            if (i == k) En = (j == k) ? p : pr;
            else if (j == k) En = -colk[m] * p;
            E[m] = En;
        }
    }
}

// ---------------------------------------------------------------------------
// Shared-memory Gauss-Jordan inverse of 16x16 SPD (one warp).
// ---------------------------------------------------------------------------
__device__ __forceinline__ void warp_inv16(float (*E)[17], int lane) {
    const int j = lane & 15, h = lane >> 4;
    for (int k = 0; k < 16; k++) {
        float p = 1.0f / E[k][k];
        float rowk = E[k][j];
        float colk[8];
#pragma unroll
        for (int m = 0; m < 8; m++) colk[m] = E[2 * m + h][k];
        __syncwarp();
#pragma unroll
        for (int m = 0; m < 8; m++) {
            int i = 2 * m + h;
            float val;
            if (i == k) {
                val = (j == k) ? p : rowk * p;
            } else if (j == k) {
                val = -colk[m] * p;
            } else {
                val = E[i][j] - colk[m] * (p * rowk);
            }
            E[i][j] = val;
        }
        __syncwarp();
    }
}

// ---------------------------------------------------------------------------
// Register-column MGS QR (positive-diagonal R, matching reference sign fix).
// ---------------------------------------------------------------------------
__device__ __forceinline__ void warp_qr_reg(float x[16], float (*Qs)[17], int lane) {
    const unsigned FULL = 0xffffffffu;
    const int j = lane & 15;
#pragma unroll
    for (int k = 0; k < 16; k++) {
        float qk[16];
#pragma unroll
        for (int i = 0; i < 16; i++) qk[i] = __shfl_sync(FULL, x[i], k);
        float nrm = 0.f;
#pragma unroll
        for (int i = 0; i < 16; i++) nrm += qk[i] * qk[i];
        float inv = rsqrtf(nrm);
#pragma unroll
        for (int i = 0; i < 16; i++) qk[i] *= inv;
        if (lane == k) {
#pragma unroll
            for (int i = 0; i < 16; i++) Qs[i][k] = qk[i];
        }
        float dot = 0.f;
#pragma unroll
        for (int i = 0; i < 16; i++) dot += qk[i] * x[i];
        if (j > k) {
#pragma unroll
            for (int i = 0; i < 16; i++) x[i] -= dot * qk[i];
        }
    }
}

// ---------------------------------------------------------------------------
// Shared-memory role overlays
// ---------------------------------------------------------------------------
struct PrepSmem {
    float sQ[16][17], sU[16][17], sW[16][17], sA[16][17];
    float sZ[16][17], sT[16][17], sRc[16][17], sGc[16][17], sJ0[16][17];
    float s1[16], s2[16], nxis[16], nais[32];
};
struct GainsSmem {
    float sE[16][17], sD[16][33], sK[16][33], sA[16][17];
    float sCA[32][17], sCB[32][9], sW[16][9];
    float sa[256 * 33];
};
struct MeansSmem {
    float sMT[CH * 256];      // 32 KB
    float sV[8 * CH * 16];    // 16 KB
};
#define SMEM_BYTES (sizeof(GainsSmem) > sizeof(MeansSmem) ? \
    (sizeof(GainsSmem) > sizeof(PrepSmem) ? sizeof(GainsSmem) : sizeof(PrepSmem)) : \
    (sizeof(MeansSmem) > sizeof(PrepSmem) ? sizeof(MeansSmem) : sizeof(PrepSmem)))

// ---------------------------------------------------------------------------
// Role 0 (block 0, all 256 threads for prep; warp 0 for riccati).
// ---------------------------------------------------------------------------
__device__ void prep_riccati_body(
    char* raw,
    const float* __restrict__ Mmat, const float* __restrict__ Nmat,
    const float* __restrict__ dvec, const float* __restrict__ Bmat,
    const float* __restrict__ Cmat,
    const float* __restrict__ nx, const float* __restrict__ na,
    const float* __restrict__ cov0) {
    PrepSmem* S = reinterpret_cast<PrepSmem*>(raw);
    const int tid = threadIdx.x;
    const int wid = tid >> 5;
    const int lane = tid & 31;
    const int i16 = tid >> 4;   // 0..15 row index for element-per-thread phases
    const int j16 = tid & 15;   // 0..15 col index

    // ======== Phase 1: independent pieces, one warp each ========
    if (wid == 0) {
        float x[16];
#pragma unroll
        for (int i = 0; i < 16; i++) x[i] = Mmat[i * 16 + (lane & 15)];
        warp_qr_reg(x, S->sQ, lane);
    } else if (wid == 1) {
        float x[16];
#pragma unroll
        for (int i = 0; i < 16; i++) x[i] = Nmat[i * 16 + (lane & 15)];
        warp_qr_reg(x, S->sU, lane);
    } else if (wid == 2) {
        if (lane < 16) {
            float dsp = softplusf(dvec[lane]);
            S->s1[lane] = sqrtf(dsp);
            S->s2[lane] = 1.0f / sqrtf(1.0f + dsp);
            S->nxis[lane] = 1.0f / (softplusf(nx[lane]) + 1e-4f);
        }
        S->nais[lane] = 1.0f / (softplusf(na[lane]) + 1e-4f);
    } else if (wid == 3) {
        // J0 = inv(cov0[0])
        for (int e = lane; e < 256; e += 32) S->sJ0[e >> 4][e & 15] = cov0[e];
        __syncwarp();
        warp_inv16(S->sJ0, lane);
    } else if (wid == 4) {
        // CB = C*B (32x8): lane = C row
        float Crow[16];
#pragma unroll
        for (int k = 0; k < 16; k++) Crow[k] = Cmat[lane * 16 + k];
#pragma unroll
        for (int jj = 0; jj < 8; jj++) {
            float s = 0.f;
#pragma unroll
            for (int k = 0; k < 16; k++) s += Crow[k] * Bmat[k * 8 + jj];
            gCB[lane * 8 + jj] = s;
        }
    }
    __syncthreads();

    // ======== Phase 2: W = Uq diag(s1) Q ; Gc = C^T diag(nai) C ; gD ========
    {
        float s = 0.f;
#pragma unroll
        for (int k = 0; k < 16; k++) s += S->sU[i16][k] * S->s1[k] * S->sQ[k][j16];
        S->sW[i16][j16] = s;
        float g = 0.f;
#pragma unroll
        for (int c = 0; c < 32; c++)
            g += Cmat[c * 16 + i16] * S->nais[c] * Cmat[c * 16 + j16];
        S->sGc[i16][j16] = g;
#pragma unroll
        for (int r = 0; r < 2; r++) {
            int e = tid + r * 256;
            int di = e >> 5, dc = e & 31;
            gD[di * 32 + dc] = Cmat[dc * 16 + di] * S->nais[dc];
        }
    }
    __syncthreads();

    // ======== Phase 3: A = W diag(s2) Uq^T ========
    {
        float s = 0.f;
#pragma unroll
        for (int k = 0; k < 16; k++) s += S->sW[i16][k] * S->s2[k] * S->sU[j16][k];
        S->sA[i16][j16] = s;
        gA[i16 * 16 + j16] = s;
    }
    __syncthreads();

    // ======== Phase 4: Z, R0, CA ========
    {
        S->sZ[i16][j16] = S->nxis[i16] * S->sA[i16][j16];
        float s = 0.f;
#pragma unroll
        for (int k = 0; k < 16; k++)
            s += S->sA[k][i16] * S->nxis[k] * S->sA[k][j16];
        S->sRc[i16][j16] = s;
#pragma unroll
        for (int r = 0; r < 2; r++) {
            int e = tid + r * 256;
            int c = e >> 4, jj = e & 15;
            float sca = 0.f;
#pragma unroll
            for (int k = 0; k < 16; k++) sca += Cmat[c * 16 + k] * S->sA[k][jj];
            gCA[c * 16 + jj] = sca;
        }
    }
    // Publish constants (gA, gD, gCA, gCB)
    __threadfence();
    __syncthreads();
    if (tid == 0) atomicExch(&gPrepFlag, 1);

    // ======== Phase 5: Riccati, warp 0 only — register-lean (no spills) ========
    if (wid != 0) return;
    const int j = lane & 15, h = lane >> 4;
    float Jr[8];
#pragma unroll
    for (int m = 0; m < 8; m++) Jr[m] = S->sJ0[(h << 3) + m][j];
    float nxij = S->nxis[j];
    __syncwarp();

    for (int t = 0; t < T0; t++) {
        float E[8];
#pragma unroll
        for (int m = 0; m < 8; m++) E[m] = Jr[m] + S->sRc[(h << 3) + m][j];
        reg_inv16(E, j, h);

        // F -> shared (sT doubles as F buffer)
#pragma unroll
        for (int m = 0; m < 8; m++) S->sT[(h << 3) + m][j] = E[m];
        __syncwarp();

        // Tm[i][j] = sum_k Z[i][k] * F[k][j]  (both operands from shared)
        float Tm[8];
#pragma unroll
        for (int m = 0; m < 8; m++) {
            int i = (h << 3) + m;
            float s0 = 0.f, s1a = 0.f;
#pragma unroll
            for (int k = 0; k < 8; k++) {
                s0 += S->sZ[i][2 * k] * S->sT[2 * k][j];
                s1a += S->sZ[i][2 * k + 1] * S->sT[2 * k + 1][j];
            }
            Tm[m] = s0 + s1a;
        }
        __syncwarp();
        // stash T in sW (free after prep)
#pragma unroll
        for (int m = 0; m < 8; m++) S->sW[(h << 3) + m][j] = Tm[m];
        __syncwarp();

        // Jm[i][j] = nxi_ij - sum_k T[i][k] * Z[j][k] ; J = Jm + G (stored)
        float* gj = gJ + t * 256;
#pragma unroll
        for (int m = 0; m < 8; m++) {
            int i = (h << 3) + m;
            float s0 = (i == j) ? nxij : 0.f, s1a = 0.f;
#pragma unroll
            for (int k = 0; k < 8; k++) {
                s0 -= S->sW[i][2 * k] * S->sZ[j][2 * k];
                s1a -= S->sW[i][2 * k + 1] * S->sZ[j][2 * k + 1];
            }
            float jn = s0 + s1a + S->sGc[i][j];
            gj[i * 16 + j] = jn;
            Jr[m] = jn;
        }
        __threadfence();
        __syncwarp();
        if (lane == 0) atomicExch(&gStepFlag[t], 1);
    }
}

// ---------------------------------------------------------------------------
// Role 1 (blocks 1..TT): per-t gains + v.
// ---------------------------------------------------------------------------
__device__ void gainsv_body(char* raw, int t,
                            const float* __restrict__ Bmat,
                            const float* __restrict__ u,
                            const float* __restrict__ a) {
    GainsSmem* S = reinterpret_cast<GainsSmem*>(raw);
    const int ts = (t < T0) ? t : (T0 - 1);
    const int tid = threadIdx.x;
    const int lane = tid & 31;

    if (tid < 32) {
        if (lane == 0) wait_flag(&gPrepFlag);
        __syncwarp();
        __threadfence();
        for (int e = lane; e < 512; e += 32) S->sD[e >> 5][e & 31] = gD[e];
        for (int e = lane; e < 256; e += 32) S->sA[e >> 4][e & 15] = gA[e];
        for (int e = lane; e < 512; e += 32) S->sCA[e >> 4][e & 15] = gCA[e];
        for (int e = lane; e < 256; e += 32) S->sCB[e >> 3][e & 7] = gCB[e];
        if (lane == 0) wait_flag(&gStepFlag[ts]);
        __syncwarp();
        __threadfence();
        for (int e = lane; e < 256; e += 32) S->sE[e >> 4][e & 15] = gJ[ts * 256 + e];
        __syncwarp();
        warp_inv16(S->sE, lane);
#pragma unroll
        for (int r = 0; r < 16; r++) {
            float s = 0.f;
#pragma unroll
            for (int m = 0; m < 16; m++) s += S->sE[r][m] * S->sD[m][lane];
            S->sK[r][lane] = s;
        }
    } else {
        for (int e = tid - 32; e < 256 * 32; e += 224) {
            int b = e >> 5, c = e & 31;
            S->sa[b * 33 + c] = a[((size_t)b * TT + t) * 32 + c];
        }
    }
    __syncthreads();

    // M (256 elems) and W (128 elems)
    {
        int i = tid & 15, jj = tid >> 4;
        float s = S->sA[i][jj];
#pragma unroll
        for (int l = 0; l < 32; l++) s -= S->sK[i][l] * S->sCA[l][jj];
        gMT[t * 256 + tid] = s;
    }
    if (tid < 128) {
        int i = tid >> 3, jw = tid & 7;
        float s = Bmat[i * 8 + jw];
#pragma unroll
        for (int l = 0; l < 32; l++) s -= S->sK[i][l] * S->sCB[l][jw];
        S->sW[i][jw] = s;
    }
    __syncthreads();

    // v_{b,t}: thread = b
    {
        const int b = tid;
        const float4* up = reinterpret_cast<const float4*>(u + ((size_t)b * TT + t) * 8);
        float4 u0 = up[0], u1 = up[1];
        float uu[8] = {u0.x, u0.y, u0.z, u0.w, u1.x, u1.y, u1.z, u1.w};
        float aa[32];
#pragma unroll
        for (int c = 0; c < 32; c++) aa[c] = S->sa[b * 33 + c];
        float v[16];
#pragma unroll
        for (int i = 0; i < 16; i++) {
            float s = 0.f;
#pragma unroll
            for (int k = 0; k < 8; k++) s += S->sW[i][k] * uu[k];
#pragma unroll
            for (int l = 0; l < 32; l++) s += S->sK[i][l] * aa[l];
            v[i] = s;
        }
        float4* vp = reinterpret_cast<float4*>(gV + ((size_t)t * BB + b) * 16);
#pragma unroll
        for (int q = 0; q < 4; q++)
            vp[q] = make_float4(v[4 * q], v[4 * q + 1], v[4 * q + 2], v[4 * q + 3]);
    }

    __threadfence();
    __syncthreads();
    if (tid == 0) atomicExch(&gGainsFlag[t], 1);
}

// ---------------------------------------------------------------------------
// Role 2 (blocks TT+1 .. TT+32): mean recurrence, 8 batches per block.
// CH=32 -> only 8 wait/load/sync rounds on the critical path.
// ---------------------------------------------------------------------------
__device__ void means_body(char* raw, int mb,
                           const float* __restrict__ mean0,
                           float* __restrict__ out) {
    MeansSmem* S = reinterpret_cast<MeansSmem*>(raw);
    const unsigned FULL = 0xffffffffu;
    const int w = threadIdx.x >> 5;
    const int lane = threadIdx.x & 31;
    const int i = lane & 15;
    const int b = mb * 8 + w;

    float mean = mean0[b * 16 + i];
    float* ob = out + (size_t)b * TT * 16;

    for (int c = 0; c < TT / CH; c++) {
        if (threadIdx.x < CH) wait_flag(&gGainsFlag[c * CH + threadIdx.x]);
        __syncthreads();
        __threadfence();
        for (int e = threadIdx.x; e < CH * 256; e += 256)
            S->sMT[e] = gMT[c * (CH * 256) + e];
        for (int e = threadIdx.x; e < 8 * CH * 16; e += 256) {
            int wb = e >> 9;           // CH*16 == 512
            int rem = e & 511;
            int tt = rem >> 4, ii = rem & 15;
            S->sV[e] = gV[((size_t)(c * CH + tt) * BB + (mb * 8 + wb)) * 16 + ii];
        }
        __syncthreads();

#pragma unroll 4
        for (int tt = 0; tt < CH; tt++) {
            const float* Mp = &S->sMT[tt * 256];
            float a0 = S->sV[(w * CH + tt) * 16 + i], a1 = 0.f, a2 = 0.f, a3 = 0.f;
#pragma unroll
            for (int k = 0; k < 4; k++) {
                a0 += Mp[(4 * k + 0) * 16 + i] * __shfl_sync(FULL, mean, 4 * k + 0, 16);
                a1 += Mp[(4 * k + 1) * 16 + i] * __shfl_sync(FULL, mean, 4 * k + 1, 16);
                a2 += Mp[(4 * k + 2) * 16 + i] * __shfl_sync(FULL, mean, 4 * k + 2, 16);
                a3 += Mp[(4 * k + 3) * 16 + i] * __shfl_sync(FULL, mean, 4 * k + 3, 16);
            }
            mean = (a0 + a1) + (a2 + a3);
            if (lane < 16) ob[(c * CH + tt) * 16 + i] = mean;
        }
        __syncthreads();
    }
}

// ---------------------------------------------------------------------------
// Flag-clear kernel (runs before the fused kernel each launch)
// ---------------------------------------------------------------------------
__global__ void clear_kernel() {
    int i = threadIdx.x;
    if (i < TT) gGainsFlag[i] = 0;
    if (i < T0) gStepFlag[i] = 0;
    if (i == 0) gPrepFlag = 0;
}

// ---------------------------------------------------------------------------
// Fused mega-kernel: 1 + TT + 32 blocks.
// ---------------------------------------------------------------------------
__global__ void __launch_bounds__(256) fused_kernel(
    const float* __restrict__ mean0, const float* __restrict__ cov0,
    const float* __restrict__ u, const float* __restrict__ a,
    const float* __restrict__ Mmat, const float* __restrict__ Nmat,
    const float* __restrict__ dvec, const float* __restrict__ Bmat,
    const float* __restrict__ Cmat,
    const float* __restrict__ nx, const float* __restrict__ na,
    float* __restrict__ out) {
    __shared__ __align__(16) char raw[SMEM_BYTES];
    const int bid = blockIdx.x;
    if (bid == 0) {
        prep_riccati_body(raw, Mmat, Nmat, dvec, Bmat, Cmat, nx, na, cov0);
    } else if (bid <= TT) {
        gainsv_body(raw, bid - 1, Bmat, u, a);
    } else {
        means_body(raw, bid - 1 - TT, mean0, out);
    }
}

// ---------------------------------------------------------------------------
extern "C" void kernel_launch(void* const* d_in, const int* in_sizes, int n_in,
                              void* d_out, int out_size) {
    const float* mean0 = (const float*)d_in[0];
    const float* cov0  = (const float*)d_in[1];
    const float* u     = (const float*)d_in[2];
    const float* a     = (const float*)d_in[3];
    const float* Mmat  = (const float*)d_in[4];
    const float* Nmat  = (const float*)d_in[5];
    const float* dvec  = (const float*)d_in[6];
    const float* Bmat  = (const float*)d_in[7];
    const float* Cmat  = (const float*)d_in[8];
    const float* nx    = (const float*)d_in[9];
    const float* na    = (const float*)d_in[10];
    float* out = (float*)d_out;

    clear_kernel<<<1, 256>>>();
    fused_kernel<<<1 + TT + 32, 256>>>(mean0, cov0, u, a, Mmat, Nmat, dvec,
                                       Bmat, Cmat, nx, na, out);
}